// round 1
// baseline (speedup 1.0000x reference)
#include <cuda_runtime.h>

// S4 kernel materialization:
//   K[h,l] = 2 * Re( sum_n Cc[h,n] * exp(dtA[h,n])^l ),  Cc = C * (exp(dtA)-1)/A
// Factor l = 64*q + r  ->  per-h 64x64x64 real GEMM:
//   K[h, 64q+r] = sum_{j=0..63} A[q][j] * B[j][r]
//   A[q][2n]=Re z^{64q}, A[q][2n+1]=Im z^{64q}
//   B[2n][r]=2*Re(Cc z^r), B[2n+1][r]=-2*Im(Cc z^r)

#define Hh   1024
#define NHn  32
#define Ll   4096

__global__ __launch_bounds__(256, 4)
void s4_vandermonde_gemm(const float* __restrict__ Cin,        // [H, NH, 2]
                         const float* __restrict__ log_dt,     // [H]
                         const float* __restrict__ log_A_real, // [H, NH]
                         const float* __restrict__ A_imag,     // [H, NH]
                         float* __restrict__ out)              // [H, L]
{
    __shared__ float Ash[64][64];   // Ash[j][q]
    __shared__ float Bsh[64][64];   // Bsh[j][r]
    __shared__ float s_dtar[NHn], s_dtai[NHn], s_cr[NHn], s_ci[NHn];

    const int h   = blockIdx.x;
    const int tid = threadIdx.x;

    // ---- per-n parameters (32 threads) ----
    if (tid < NHn) {
        int n = tid;
        float dt   = expf(log_dt[h]);
        float Are  = -expf(log_A_real[h * NHn + n]);   // Re(A)
        float Aim  = -A_imag[h * NHn + n];             // Im(A)
        float dtar = Are * dt;
        float dtai = Aim * dt;

        // e = exp(dtA)
        float er = expf(dtar);
        float sn, cs;
        sincosf(dtai, &sn, &cs);
        float e_re = er * cs;
        float e_im = er * sn;

        // f = (e - 1) / A = (e-1) * conj(A) / |A|^2
        float num_re = e_re - 1.0f;
        float num_im = e_im;
        float inv    = 1.0f / (Are * Are + Aim * Aim);
        float f_re   = (num_re * Are + num_im * Aim) * inv;
        float f_im   = (num_im * Are - num_re * Aim) * inv;

        // Cc = (C0 + i C1) * f
        float c0 = Cin[(h * NHn + n) * 2 + 0];
        float c1 = Cin[(h * NHn + n) * 2 + 1];
        s_cr[n]   = c0 * f_re - c1 * f_im;
        s_ci[n]   = c0 * f_im + c1 * f_re;
        s_dtar[n] = dtar;
        s_dtai[n] = dtai;
    }
    __syncthreads();

    // ---- build tables: A (z^{64q}) and B (Cc * z^r) ----
    // NH*64 = 2048 (n, idx) pairs, 256 threads -> 8 each
    #pragma unroll
    for (int k = 0; k < 8; k++) {
        int idx = tid + k * 256;
        int n   = idx >> 6;
        int q   = idx & 63;
        float dtar = s_dtar[n];
        float dtai = s_dtai[n];

        // Q = exp(dtA * 64q)
        float tq  = 64.0f * (float)q;
        float mag = expf(dtar * tq);
        float sq, cq;
        sincosf(dtai * tq, &sq, &cq);
        Ash[2 * n    ][q] = mag * cq;
        Ash[2 * n + 1][q] = mag * sq;

        // P = Cc * exp(dtA * r), r == q index reuse
        float tr   = (float)q;
        float magr = expf(dtar * tr);
        float sr, cr;
        sincosf(dtai * tr, &sr, &cr);
        float pr = magr * cr;
        float pi = magr * sr;
        float ccr = s_cr[n];
        float cci = s_ci[n];
        Bsh[2 * n    ][q] =  2.0f * (ccr * pr - cci * pi);
        Bsh[2 * n + 1][q] = -2.0f * (ccr * pi + cci * pr);
    }
    __syncthreads();

    // ---- 64x64x64 GEMM: thread (tx,ty) computes 4x4 tile at (q=4ty.., r=4tx..) ----
    const int tx = tid & 15;
    const int ty = tid >> 4;
    const int rb = tx * 4;
    const int qb = ty * 4;

    float acc00 = 0.f, acc01 = 0.f, acc02 = 0.f, acc03 = 0.f;
    float acc10 = 0.f, acc11 = 0.f, acc12 = 0.f, acc13 = 0.f;
    float acc20 = 0.f, acc21 = 0.f, acc22 = 0.f, acc23 = 0.f;
    float acc30 = 0.f, acc31 = 0.f, acc32 = 0.f, acc33 = 0.f;

    #pragma unroll 16
    for (int j = 0; j < 64; j++) {
        float4 a = *(const float4*)&Ash[j][qb];
        float4 b = *(const float4*)&Bsh[j][rb];
        acc00 = fmaf(a.x, b.x, acc00);
        acc01 = fmaf(a.x, b.y, acc01);
        acc02 = fmaf(a.x, b.z, acc02);
        acc03 = fmaf(a.x, b.w, acc03);
        acc10 = fmaf(a.y, b.x, acc10);
        acc11 = fmaf(a.y, b.y, acc11);
        acc12 = fmaf(a.y, b.z, acc12);
        acc13 = fmaf(a.y, b.w, acc13);
        acc20 = fmaf(a.z, b.x, acc20);
        acc21 = fmaf(a.z, b.y, acc21);
        acc22 = fmaf(a.z, b.z, acc22);
        acc23 = fmaf(a.z, b.w, acc23);
        acc30 = fmaf(a.w, b.x, acc30);
        acc31 = fmaf(a.w, b.y, acc31);
        acc32 = fmaf(a.w, b.z, acc32);
        acc33 = fmaf(a.w, b.w, acc33);
    }

    // ---- store: out[h, 64*q + r] ----
    float* o = out + (size_t)h * Ll;
    float4 v0 = make_float4(acc00, acc01, acc02, acc03);
    float4 v1 = make_float4(acc10, acc11, acc12, acc13);
    float4 v2 = make_float4(acc20, acc21, acc22, acc23);
    float4 v3 = make_float4(acc30, acc31, acc32, acc33);
    *(float4*)&o[(qb + 0) * 64 + rb] = v0;
    *(float4*)&o[(qb + 1) * 64 + rb] = v1;
    *(float4*)&o[(qb + 2) * 64 + rb] = v2;
    *(float4*)&o[(qb + 3) * 64 + rb] = v3;
}

extern "C" void kernel_launch(void* const* d_in, const int* in_sizes, int n_in,
                              void* d_out, int out_size)
{
    const float* C          = (const float*)d_in[0];   // [H, NH, 2]
    const float* log_dt     = (const float*)d_in[1];   // [H]
    const float* log_A_real = (const float*)d_in[2];   // [H, NH]
    const float* A_imag     = (const float*)d_in[3];   // [H, NH]
    float* out              = (float*)d_out;           // [H, L]

    s4_vandermonde_gemm<<<Hh, 256>>>(C, log_dt, log_A_real, A_imag, out);
}